// round 12
// baseline (speedup 1.0000x reference)
#include <cuda_runtime.h>

// SSD post-processing: decode + per-class greedy NMS.
//   loc_data  [8, 3000, 4]  f32
//   conf_data [8, 3000, 21] f32
//   priors    [3000, 4]     f32
//   out       [8, 21, 200, 5] f32  (score, x1, y1, x2, y2), zero-padded
//
// One CTA per (class, batch), grid (21, 8), 256 threads.
// R9 kernel with EXACTLY ONE change: Phase B's serial resolution (warp-0 smem
// scan + 2 block barriers PER ACCEPT, ~1300 cyc/accept, ~180us/CTA) is
// replaced by a warp-0 register resolver: tile alive bits live in one register
// per lane (bit m <=> candidate m*32+lane), next accept = ffs + redux.min +
// ballot, box broadcast via 4 shfls, self-suppression = 8 register IoUs/lane.
// 2 block barriers per TILE total. Naive sort and Phase A are unchanged
// (R3==R9 proved they are not the bottleneck).

#define NP    3000
#define NPAD  4096
#define NC    21
#define TOPK  200
#define NT    256
#define NWARP (NT / 32)

typedef unsigned long long ull;

// reference-exact IoU (no FMA contraction)
__device__ __forceinline__ float iou_rn(float ax1, float ay1, float ax2, float ay2, float aa,
                                        float bx1, float by1, float bx2, float by2, float ba)
{
    float ltx = fmaxf(ax1, bx1);
    float lty = fmaxf(ay1, by1);
    float rbx = fminf(ax2, bx2);
    float rby = fminf(ay2, by2);
    float wx  = fmaxf(__fsub_rn(rbx, ltx), 0.0f);
    float wy  = fmaxf(__fsub_rn(rby, lty), 0.0f);
    float inter = __fmul_rn(wx, wy);
    float uni   = __fsub_rn(__fadd_rn(aa, ba), inter);
    return __fdiv_rn(inter, fmaxf(uni, 1e-12f));
}

__global__ __launch_bounds__(NT, 2) void ssd_post_kernel(
    const float* __restrict__ loc,
    const float* __restrict__ conf,
    const float* __restrict__ priors,
    float* __restrict__ out)
{
    __shared__ ull    keys[NPAD];     // 32 KB
    __shared__ float4 sbox[NT];       // tile candidate boxes (4 KB)
    __shared__ float  sare[NT];       // tile candidate areas (1 KB)
    __shared__ float  ssc[NT];        // tile candidate scores (1 KB)
    __shared__ float4 abox[TOPK];     // accepted boxes (3.2 KB)
    __shared__ float  aare[TOPK];     // accepted areas (0.8 KB)
    __shared__ int    salv[NWARP];    // per-warp alive ballots
    __shared__ int    s_cnt;
    __shared__ int    s_nvalid;

    const int c    = blockIdx.x;
    const int b    = blockIdx.y;
    const int tid  = threadIdx.x;
    const int lane = tid & 31;
    const int wix  = tid >> 5;

    float* outp = out + (size_t)(b * NC + c) * (TOPK * 5);
    for (int k = tid; k < TOPK * 5; k += NT) outp[k] = 0.0f;
    if (c == 0) return;  // background class: zeros only

    if (tid == 0) { s_nvalid = 0; s_cnt = 0; }
    __syncthreads();

    // ---- build sort keys: (sortable(score) << 32) | ~idx  (stable desc) ----
    const float* confb = conf + (size_t)b * NP * NC + c;
    int myValid = 0;
    for (int p = tid; p < NPAD; p += NT) {
        ull key = 0ULL;                               // padding: below everything
        if (p < NP) {
            float s = confb[(size_t)p * NC];
            bool v = (s > 0.01f);
            myValid += v ? 1 : 0;
            if (!v) s = __int_as_float(0xff800000);   // -inf: sorts after valid
            unsigned u = __float_as_uint(s);
            u = (u & 0x80000000u) ? ~u : (u | 0x80000000u);
            key = ((ull)u << 32) | (unsigned)(~p);
        }
        keys[p] = key;
    }
    #pragma unroll
    for (int o = 16; o > 0; o >>= 1)
        myValid += __shfl_down_sync(0xffffffffu, myValid, o);
    if (lane == 0 && myValid) atomicAdd(&s_nvalid, myValid);
    __syncthreads();

    // ---- bitonic sort, descending, 4096 u64 keys (naive, measured-cheap) ----
    for (int k = 2; k <= NPAD; k <<= 1) {
        for (int j = k >> 1; j > 0; j >>= 1) {
            #pragma unroll
            for (int w = 0; w < NPAD / NT; ++w) {
                int i = tid + w * NT;
                int ixj = i ^ j;
                if (ixj > i) {
                    ull a  = keys[i];
                    ull bb = keys[ixj];
                    bool sw = ((i & k) == 0) ? (a < bb) : (a > bb);
                    if (sw) { keys[i] = bb; keys[ixj] = a; }
                }
            }
            __syncthreads();
        }
    }

    // ---- tiled candidate-driven NMS ----
    const int nvalid = s_nvalid;   // valid candidates form the sorted prefix
    const float* locb = loc + (size_t)b * NP * 4;

    for (int tb = 0; tb < nvalid; tb += NT) {
        const int cnt0 = s_cnt;        // committed before last barrier
        if (cnt0 >= TOPK) break;       // uniform

        const int j = tb + tid;
        bool myAlive = (j < nvalid);

        // decode my candidate (exact reference op order) into regs + tile smem
        float mx1 = 0.f, my1 = 0.f, mx2 = 0.f, my2 = 0.f, mar = 0.f;
        if (myAlive) {
            ull key = keys[j];
            int idx = (int)(~(unsigned)key);
            float ms = __uint_as_float((unsigned)(key >> 32) & 0x7FFFFFFFu);
            float4 l  = *(const float4*)(locb + (size_t)idx * 4);
            float4 pr = *(const float4*)(priors + (size_t)idx * 4);
            float cx = __fadd_rn(pr.x, __fmul_rn(__fmul_rn(l.x, 0.1f), pr.z));
            float cy = __fadd_rn(pr.y, __fmul_rn(__fmul_rn(l.y, 0.1f), pr.w));
            float w  = __fmul_rn(pr.z, expf(__fmul_rn(l.z, 0.2f)));
            float hh = __fmul_rn(pr.w, expf(__fmul_rn(l.w, 0.2f)));
            mx1 = __fsub_rn(cx, __fmul_rn(0.5f, w));
            my1 = __fsub_rn(cy, __fmul_rn(0.5f, hh));
            mx2 = __fadd_rn(mx1, w);
            my2 = __fadd_rn(my1, hh);
            mar = __fmul_rn(__fsub_rn(mx2, mx1), __fsub_rn(my2, my1));
            sbox[tid] = make_float4(mx1, my1, mx2, my2);
            sare[tid] = mar;
            ssc[tid]  = ms;
        }

        // Phase A: test vs committed accepted list, early-out on overlap
        if (myAlive) {
            for (int q = 0; q < cnt0; ++q) {
                float4 ab = abox[q];
                if (iou_rn(mx1, my1, mx2, my2, mar,
                           ab.x, ab.y, ab.z, ab.w, aare[q]) > 0.45f) {
                    myAlive = false; break;
                }
            }
        }
        unsigned wm = __ballot_sync(0xffffffffu, myAlive);
        if (lane == 0) salv[wix] = (int)wm;
        __syncthreads();

        // Phase B: warp 0 resolves the whole tile in registers, barrier-free
        if (wix == 0) {
            // alive bits: bit m of lane l <=> candidate m*32+l alive
            unsigned alive8 = 0;
            #pragma unroll
            for (int m = 0; m < NWARP; ++m)
                alive8 |= (((unsigned)salv[m] >> lane) & 1u) << m;

            // my 8 candidates' boxes + areas (garbage for dead slots is fine:
            // their alive bits are 0 and stay 0)
            float4 cb[NWARP]; float ca[NWARP];
            #pragma unroll
            for (int m = 0; m < NWARP; ++m) cb[m] = sbox[m * 32 + lane];
            #pragma unroll
            for (int m = 0; m < NWARP; ++m) ca[m] = sare[m * 32 + lane];

            int cnt = cnt0;
            while (cnt < TOPK) {
                unsigned mlow  = alive8 ? (unsigned)(__ffs(alive8) - 1) : 99u;
                unsigned mstar = __reduce_min_sync(0xffffffffu, mlow);
                if (mstar == 99u) break;                 // tile exhausted
                unsigned sel = __ballot_sync(0xffffffffu, mlow == mstar);
                int L = __ffs(sel) - 1;                  // accepted = mstar*32 + L

                // uniform-index select of cb[mstar], broadcast lane L's values
                float vx1 = cb[0].x, vy1 = cb[0].y, vx2 = cb[0].z, vy2 = cb[0].w;
                #pragma unroll
                for (int m = 1; m < NWARP; ++m)
                    if (mstar == (unsigned)m) { vx1 = cb[m].x; vy1 = cb[m].y; vx2 = cb[m].z; vy2 = cb[m].w; }
                float cx1 = __shfl_sync(0xffffffffu, vx1, L);
                float cy1 = __shfl_sync(0xffffffffu, vy1, L);
                float cx2 = __shfl_sync(0xffffffffu, vx2, L);
                float cy2 = __shfl_sync(0xffffffffu, vy2, L);
                float car = __fmul_rn(__fsub_rn(cx2, cx1), __fsub_rn(cy2, cy1));

                if (lane == L) {
                    abox[cnt] = make_float4(cx1, cy1, cx2, cy2);
                    aare[cnt] = car;
                    float* o = outp + cnt * 5;
                    o[0] = ssc[mstar * 32 + lane];
                    o[1] = cx1; o[2] = cy1; o[3] = cx2; o[4] = cy2;
                }

                // suppress my candidates vs the new accept (self iou=1 clears it)
                unsigned kill = 0;
                #pragma unroll
                for (int m = 0; m < NWARP; ++m) {
                    float ii = iou_rn(cb[m].x, cb[m].y, cb[m].z, cb[m].w, ca[m],
                                      cx1, cy1, cx2, cy2, car);
                    if (ii > 0.45f) kill |= (1u << m);
                }
                alive8 &= ~kill;
                cnt++;
            }
            if (lane == 0) s_cnt = cnt;
        }
        __syncthreads();   // publish abox/aare/s_cnt to next tile's Phase A
    }
}

extern "C" void kernel_launch(void* const* d_in, const int* in_sizes, int n_in,
                              void* d_out, int out_size)
{
    const float* loc = nullptr;
    const float* conf = nullptr;
    const float* priors = nullptr;
    for (int i = 0; i < n_in; i++) {
        if (in_sizes[i] == 8 * NP * 4)       loc    = (const float*)d_in[i];
        else if (in_sizes[i] == 8 * NP * NC) conf   = (const float*)d_in[i];
        else if (in_sizes[i] == NP * 4)      priors = (const float*)d_in[i];
    }
    float* out = (float*)d_out;

    dim3 grid(NC, 8);
    ssd_post_kernel<<<grid, NT>>>(loc, conf, priors, out);
}

// round 13
// speedup vs baseline: 2.1853x; 2.1853x over previous
#include <cuda_runtime.h>

// SSD post-processing: decode + per-class greedy NMS.
//   loc_data  [8, 3000, 4]  f32
//   conf_data [8, 3000, 21] f32
//   priors    [3000, 4]     f32
//   out       [8, 21, 200, 5] f32  (score, x1, y1, x2, y2), zero-padded
//
// One CTA per (class, batch), grid (21, 8), 256 threads.
// R9 structure (parallel Phase A + serial in-order accepts with block-wide
// parallel suppression -- the only structure that has ever hit 227us), with
// two local changes:
//   (a) ONE barrier per accept: next-accept index is computed redundantly by
//       every warp from the 8 published ballot words (LDS+ballot+shfl+ffs),
//       removing the warp0-scan -> s_i -> barrier -> read chain.
//   (b) register-fused bitonic sort (R4's verbatim, bit-identical results):
//       strides <=8 in registers (16 keys/thread), XOR bank swizzle;
//       smem substages 78 -> 36, barriers 78 -> ~46.

#define NP    3000
#define NPAD  4096
#define NC    21
#define TOPK  200
#define NT    256
#define NWARP (NT / 32)
#define EPT   (NPAD / NT)                 // 16 keys per thread
#define SW(i) ((i) ^ (((i) >> 4) & 15))   // bank swizzle for u64 keys[]

typedef unsigned long long ull;

__device__ __forceinline__ void cexch(ull& a, ull& b, bool desc) {
    if (desc ? (a < b) : (a > b)) { ull t = a; a = b; b = t; }
}

// reference-exact IoU (no FMA contraction)
__device__ __forceinline__ float iou_rn(float ax1, float ay1, float ax2, float ay2, float aa,
                                        float bx1, float by1, float bx2, float by2, float ba)
{
    float ltx = fmaxf(ax1, bx1);
    float lty = fmaxf(ay1, by1);
    float rbx = fminf(ax2, bx2);
    float rby = fminf(ay2, by2);
    float wx  = fmaxf(__fsub_rn(rbx, ltx), 0.0f);
    float wy  = fmaxf(__fsub_rn(rby, lty), 0.0f);
    float inter = __fmul_rn(wx, wy);
    float uni   = __fsub_rn(__fadd_rn(aa, ba), inter);
    return __fdiv_rn(inter, fmaxf(uni, 1e-12f));
}

__global__ __launch_bounds__(NT, 2) void ssd_post_kernel(
    const float* __restrict__ loc,
    const float* __restrict__ conf,
    const float* __restrict__ priors,
    float* __restrict__ out)
{
    __shared__ ull    keys[NPAD];     // 32 KB
    __shared__ float4 sbox[NT];       // tile candidate boxes
    __shared__ float  sare[NT];       // tile candidate areas
    __shared__ float4 abox[TOPK];     // accepted boxes
    __shared__ float  aare[TOPK];     // accepted areas
    __shared__ int    salv[NWARP];    // per-warp alive ballots
    __shared__ int    s_nvalid;

    const int c    = blockIdx.x;
    const int b    = blockIdx.y;
    const int tid  = threadIdx.x;
    const int lane = tid & 31;
    const int wix  = tid >> 5;

    float* outp = out + (size_t)(b * NC + c) * (TOPK * 5);
    for (int k = tid; k < TOPK * 5; k += NT) outp[k] = 0.0f;
    if (c == 0) return;  // background class: zeros only

    if (tid == 0) s_nvalid = 0;
    __syncthreads();

    // ---- build sort keys: (sortable(score) << 32) | ~idx  (stable desc) ----
    const float* confb = conf + (size_t)b * NP * NC + c;
    int myValid = 0;
    #pragma unroll
    for (int w = 0; w < EPT; ++w) {
        int p = tid + w * NT;
        ull key = 0ULL;                               // padding: below everything
        if (p < NP) {
            float s = confb[(size_t)p * NC];
            bool v = (s > 0.01f);
            myValid += v ? 1 : 0;
            if (!v) s = __int_as_float(0xff800000);   // -inf: sorts after valid
            unsigned u = __float_as_uint(s);
            u = (u & 0x80000000u) ? ~u : (u | 0x80000000u);
            key = ((ull)u << 32) | (unsigned)(~p);
        }
        keys[SW(p)] = key;
    }
    #pragma unroll
    for (int o = 16; o > 0; o >>= 1)
        myValid += __shfl_down_sync(0xffffffffu, myValid, o);
    if (lane == 0 && myValid) atomicAdd(&s_nvalid, myValid);
    __syncthreads();

    // ---- bitonic sort, descending (register-fused, R4-verbatim) ----
    // fused register-local stages k = 2..16 (all strides < 16)
    {
        const int base = tid * EPT;
        ull r[EPT];
        #pragma unroll
        for (int m = 0; m < EPT; ++m) r[m] = keys[SW(base + m)];
        #pragma unroll
        for (int k = 2; k <= 16; k <<= 1) {
            #pragma unroll
            for (int j = k >> 1; j >= 1; j >>= 1) {
                #pragma unroll
                for (int m = 0; m < EPT; ++m)
                    if (!(m & j))
                        cexch(r[m], r[m | j], ((base + m) & k) == 0);
            }
        }
        #pragma unroll
        for (int m = 0; m < EPT; ++m) keys[SW(base + m)] = r[m];
    }
    __syncthreads();

    for (int k = 32; k <= NPAD; k <<= 1) {
        // smem substages: strides >= 16, pair-expanded (all threads active)
        for (int j = k >> 1; j >= 16; j >>= 1) {
            #pragma unroll
            for (int w = 0; w < NPAD / (2 * NT); ++w) {
                int p   = tid + w * NT;
                int i   = ((p & ~(j - 1)) << 1) | (p & (j - 1));
                int ixj = i | j;
                ull a  = keys[SW(i)];
                ull bb = keys[SW(ixj)];
                if (((i & k) == 0) ? (a < bb) : (a > bb)) {
                    keys[SW(i)] = bb; keys[SW(ixj)] = a;
                }
            }
            __syncthreads();
        }
        // register-local tail: strides 8,4,2,1 (uniform direction per thread)
        {
            const int  base = tid * EPT;
            const bool desc = ((base & k) == 0);
            ull r[EPT];
            #pragma unroll
            for (int m = 0; m < EPT; ++m) r[m] = keys[SW(base + m)];
            #pragma unroll
            for (int j = 8; j >= 1; j >>= 1) {
                #pragma unroll
                for (int m = 0; m < EPT; ++m)
                    if (!(m & j)) cexch(r[m], r[m | j], desc);
            }
            #pragma unroll
            for (int m = 0; m < EPT; ++m) keys[SW(base + m)] = r[m];
        }
        __syncthreads();
    }

    // ---- tiled candidate-driven NMS ----
    const int nvalid = s_nvalid;   // valid candidates form the sorted prefix
    const float* locb = loc + (size_t)b * NP * 4;

    int cnt = 0;                   // uniform register across all threads

    for (int tb = 0; tb < nvalid && cnt < TOPK; tb += NT) {
        const int j = tb + tid;
        ull key = keys[SW(j)];
        bool myAlive = (j < nvalid) && ((key >> 63) != 0ULL);

        // decode my candidate (exact reference op order) into regs + tile smem
        float mx1 = 0.f, my1 = 0.f, mx2 = 0.f, my2 = 0.f, mar = 0.f, ms = 0.f;
        if (myAlive) {
            int idx = (int)(~(unsigned)key);
            ms = __uint_as_float((unsigned)(key >> 32) & 0x7FFFFFFFu);
            float4 l  = *(const float4*)(locb + (size_t)idx * 4);
            float4 pr = *(const float4*)(priors + (size_t)idx * 4);
            float cx = __fadd_rn(pr.x, __fmul_rn(__fmul_rn(l.x, 0.1f), pr.z));
            float cy = __fadd_rn(pr.y, __fmul_rn(__fmul_rn(l.y, 0.1f), pr.w));
            float w  = __fmul_rn(pr.z, expf(__fmul_rn(l.z, 0.2f)));
            float hh = __fmul_rn(pr.w, expf(__fmul_rn(l.w, 0.2f)));
            mx1 = __fsub_rn(cx, __fmul_rn(0.5f, w));
            my1 = __fsub_rn(cy, __fmul_rn(0.5f, hh));
            mx2 = __fadd_rn(mx1, w);
            my2 = __fadd_rn(my1, hh);
            mar = __fmul_rn(__fsub_rn(mx2, mx1), __fsub_rn(my2, my1));
            sbox[tid] = make_float4(mx1, my1, mx2, my2);
            sare[tid] = mar;
        }

        // Phase A: test vs committed accepted list, early-out on overlap
        if (myAlive) {
            for (int q = 0; q < cnt; ++q) {
                float4 ab = abox[q];
                if (iou_rn(mx1, my1, mx2, my2, mar,
                           ab.x, ab.y, ab.z, ab.w, aare[q]) > 0.45f) {
                    myAlive = false; break;
                }
            }
        }
        unsigned wm = __ballot_sync(0xffffffffu, myAlive);
        if (lane == 0) salv[wix] = (int)wm;
        __syncthreads();   // publish sbox/sare/salv for the accept loop

        // Serial accept loop: ONE barrier per accept.
        // Every warp redundantly finds the first alive candidate from the 8
        // published ballot words (no warp0 scan, no s_i round-trip). All
        // branch decisions read only barrier-published state => uniform.
        while (true) {
            int wv = (lane < NWARP) ? salv[lane] : 0;
            unsigned nz = __ballot_sync(0xffffffffu, wv != 0);
            if (nz == 0) break;                      // tile exhausted (uniform)
            int fw   = __ffs(nz) - 1;
            int word = __shfl_sync(0xffffffffu, wv, fw);
            int i    = (fw << 5) + __ffs(word) - 1;  // first alive candidate

            if (tid == i) {
                // accept my candidate as kept #cnt
                abox[cnt] = make_float4(mx1, my1, mx2, my2);
                aare[cnt] = mar;
                float* o = outp + cnt * 5;
                o[0] = ms; o[1] = mx1; o[2] = my1; o[3] = mx2; o[4] = my2;
                myAlive = false;
            } else if (myAlive) {
                // all alive threads have tid > i (i is the first alive)
                float4 ib = sbox[i];
                float ii = iou_rn(mx1, my1, mx2, my2, mar,
                                  ib.x, ib.y, ib.z, ib.w, sare[i]);
                if (ii > 0.45f) myAlive = false;
            }
            unsigned wm2 = __ballot_sync(0xffffffffu, myAlive);
            if (lane == 0) salv[wix] = (int)wm2;
            cnt++;                                   // uniform
            __syncthreads();                         // publish salv/abox/aare
            if (cnt >= TOPK) break;                  // uniform
        }
        __syncthreads();   // reconverge before next tile overwrites sbox/salv
    }
}

extern "C" void kernel_launch(void* const* d_in, const int* in_sizes, int n_in,
                              void* d_out, int out_size)
{
    const float* loc = nullptr;
    const float* conf = nullptr;
    const float* priors = nullptr;
    for (int i = 0; i < n_in; i++) {
        if (in_sizes[i] == 8 * NP * 4)       loc    = (const float*)d_in[i];
        else if (in_sizes[i] == 8 * NP * NC) conf   = (const float*)d_in[i];
        else if (in_sizes[i] == NP * 4)      priors = (const float*)d_in[i];
    }
    float* out = (float*)d_out;

    dim3 grid(NC, 8);
    ssd_post_kernel<<<grid, NT>>>(loc, conf, priors, out);
}